// round 1
// baseline (speedup 1.0000x reference)
#include <cuda_runtime.h>
#include <math.h>
#include <stdint.h>

#define BATCH 8192
#define NM 64
#define NN 4096          // 64*64
#define LD 65            // padded row stride for scalar-access tiles
#define LDV 68           // padded row stride for VT (float4-aligned rows)
#define EPS 1e-8f

#define K0_BLOCKS 256
#define K0_NB 32         // batches per mean-partial block
#define K2_BLOCKS 1024
#define K2_NB 8          // matrices per jacobi block
#define SWEEPS_BATCH 9
#define SWEEPS_SMALL 12

// ---------------- device scratch (static, no allocations) ----------------
__device__ float g_partial_mean[(size_t)K0_BLOCKS * NN];
__device__ float g_mean[NN];
__device__ float g_s[NN];
__device__ float g_si[NN];
__device__ float g_gsqrt[NN];
__device__ float g_W[NN];
__device__ float g_partial_t[(size_t)K2_BLOCKS * NN];
__device__ float g_tmean[NN];
__device__ unsigned char g_pairs[63 * 64];   // 63 rounds x 32 pairs x (p,q)

// ---------------- round-robin pair schedule ----------------
__global__ void gen_pairs_kernel() {
    if (threadIdx.x == 0 && blockIdx.x == 0) {
        unsigned char b[64];
        for (int r = 0; r < 63; ++r) {
            b[0] = 0;
            for (int i = 1; i < 64; ++i) b[i] = (unsigned char)(1 + (i - 1 + r) % 63);
            for (int k = 0; k < 32; ++k) {
                g_pairs[r * 64 + 2 * k]     = b[k];
                g_pairs[r * 64 + 2 * k + 1] = b[63 - k];
            }
        }
    }
}

// ---------------- block helpers (256 threads assumed) ----------------

// C = A @ B ; A,B,C are 64xLD smem tiles, C must not alias A or B.
// Caller must __syncthreads() before (inputs ready) and after (C ready).
__device__ __forceinline__ void mm64(const float* A, const float* B, float* C) {
    const int r  = threadIdx.x >> 2;
    const int c0 = (threadIdx.x & 3) << 4;
    float acc[16];
#pragma unroll
    for (int i = 0; i < 16; ++i) acc[i] = 0.f;
    for (int k = 0; k < 64; ++k) {
        float a = A[r * LD + k];
#pragma unroll
        for (int i = 0; i < 16; ++i) acc[i] = fmaf(a, B[k * LD + c0 + i], acc[i]);
    }
#pragma unroll
    for (int i = 0; i < 16; ++i) C[r * LD + c0 + i] = acc[i];
}

// Parallel cyclic Jacobi eigensolver for symmetric 64x64.
// A: 64xLD (in: matrix, out: ~diagonal with eigenvalues on the diagonal)
// VT: 64xLDV holds V^T (row k = eigenvector k), initialized to I here.
// cbuf/sbuf: float[32], pbuf/qbuf: uchar[32] smem scratch.
__device__ void jacobi64(float* A, float* VT, float* cbuf, float* sbuf,
                         unsigned char* pbuf, unsigned char* qbuf, int sweeps) {
    const int tid = threadIdx.x;
    for (int idx = tid; idx < NN; idx += 256) {
        int r = idx >> 6, c = idx & 63;
        VT[r * LDV + c] = (r == c) ? 1.f : 0.f;
    }
    __syncthreads();

    for (int sw = 0; sw < sweeps; ++sw) {
        for (int rr = 0; rr < 63; ++rr) {
            if (tid < 32) {
                int p = g_pairs[rr * 64 + 2 * tid];
                int q = g_pairs[rr * 64 + 2 * tid + 1];
                float app = A[p * LD + p], aqq = A[q * LD + q], apq = A[p * LD + q];
                float c, s;
                if (fabsf(apq) > 1e-36f) {
                    float th = 0.5f * (aqq - app) / apq;
                    float t  = copysignf(1.f, th) / (fabsf(th) + sqrtf(1.f + th * th));
                    c = rsqrtf(1.f + t * t);
                    s = t * c;
                } else { c = 1.f; s = 0.f; }
                cbuf[tid] = c; sbuf[tid] = s;
                pbuf[tid] = (unsigned char)p; qbuf[tid] = (unsigned char)q;
            }
            __syncthreads();
            // Fused two-sided update A <- J^T A J (1024 2x2 units)
            // + eigenvector rows VT <- J^T VT (512 float4 units)
            for (int idx = tid; idx < 1024 + 512; idx += 256) {
                if (idx < 1024) {
                    int ki = idx & 31, kj = idx >> 5;
                    int pi = pbuf[ki], qi = qbuf[ki];
                    int pj = pbuf[kj], qj = qbuf[kj];
                    float ci = cbuf[ki], si = sbuf[ki];
                    float cj = cbuf[kj], sj = sbuf[kj];
                    float a00 = A[pi * LD + pj], a01 = A[pi * LD + qj];
                    float a10 = A[qi * LD + pj], a11 = A[qi * LD + qj];
                    float b00 = ci * a00 - si * a10, b01 = ci * a01 - si * a11;
                    float b10 = si * a00 + ci * a10, b11 = si * a01 + ci * a11;
                    A[pi * LD + pj] = cj * b00 - sj * b01;
                    A[pi * LD + qj] = sj * b00 + cj * b01;
                    A[qi * LD + pj] = cj * b10 - sj * b11;
                    A[qi * LD + qj] = sj * b10 + cj * b11;
                } else {
                    int u  = idx - 1024;
                    int k  = u >> 4;
                    int c4 = (u & 15) << 2;
                    int p = pbuf[k], q = qbuf[k];
                    float c = cbuf[k], s = sbuf[k];
                    float4 vp = *(float4*)&VT[p * LDV + c4];
                    float4 vq = *(float4*)&VT[q * LDV + c4];
                    float4 np, nq;
                    np.x = c * vp.x - s * vq.x; np.y = c * vp.y - s * vq.y;
                    np.z = c * vp.z - s * vq.z; np.w = c * vp.w - s * vq.w;
                    nq.x = s * vp.x + c * vq.x; nq.y = s * vp.y + c * vq.y;
                    nq.z = s * vp.z + c * vq.z; nq.w = s * vp.w + c * vq.w;
                    *(float4*)&VT[p * LDV + c4] = np;
                    *(float4*)&VT[q * LDV + c4] = nq;
                }
            }
            __syncthreads();
        }
    }
}

// C[i][j] = sum_k VT[k][i] * fw[k] * VT[k][j]; U is 64xLD scratch, C is 64xLD.
// Caller syncs before (fw/VT ready) and after (C ready).
__device__ __forceinline__ void recon(const float* VT, const float* fw, float* U, float* C) {
    const int tid = threadIdx.x;
    for (int idx = tid; idx < NN; idx += 256) {
        int k = idx >> 6, i = idx & 63;
        U[k * LD + i] = fw[k] * VT[k * LDV + i];
    }
    __syncthreads();
    const int r  = tid >> 2;
    const int c0 = (tid & 3) << 4;
    float acc[16];
#pragma unroll
    for (int i = 0; i < 16; ++i) acc[i] = 0.f;
    for (int k = 0; k < 64; ++k) {
        float u = U[k * LD + r];
#pragma unroll
        for (int i = 0; i < 16; ++i) acc[i] = fmaf(u, VT[k * LDV + c0 + i], acc[i]);
    }
#pragma unroll
    for (int i = 0; i < 16; ++i) C[r * LD + c0 + i] = acc[i];
}

// ---------------- kernel 0: arithmetic mean (two stage) ----------------
__global__ __launch_bounds__(256) void mean_partial_kernel(const float* __restrict__ x) {
    const int g = blockIdx.x, tid = threadIdx.x;
    float acc[16];
#pragma unroll
    for (int i = 0; i < 16; ++i) acc[i] = 0.f;
    const float* xb = x + (size_t)g * K0_NB * NN;
    for (int b = 0; b < K0_NB; ++b) {
#pragma unroll
        for (int i = 0; i < 16; ++i) acc[i] += xb[(size_t)b * NN + tid + (i << 8)];
    }
#pragma unroll
    for (int i = 0; i < 16; ++i) g_partial_mean[(size_t)g * NN + tid + (i << 8)] = acc[i];
}

__global__ void reduce_mean_kernel() {
    int j = blockIdx.x * 128 + threadIdx.x;
    float acc = 0.f;
    for (int g = 0; g < K0_BLOCKS; ++g) acc += g_partial_mean[(size_t)g * NN + j];
    g_mean[j] = acc * (1.0f / BATCH);
}

// ---------------- kernel 1: eigh(mean)->s,si ; eigh(G)->gsqrt ----------------
__global__ __launch_bounds__(256) void prep_kernel(const float* __restrict__ G) {
    extern __shared__ float sm[];
    float* A   = sm;                  // 64*LD
    float* B1  = A + 64 * LD;         // 64*LD
    float* B2  = B1 + 64 * LD;        // 64*LD
    float* VT  = B2 + 64 * LD;        // 64*LDV
    float* wbuf = VT + 64 * LDV;      // 64
    float* fw   = wbuf + 64;          // 64
    float* cbuf = fw + 64;            // 32
    float* sbuf = cbuf + 32;          // 32
    unsigned char* pbuf = (unsigned char*)(sbuf + 32);
    unsigned char* qbuf = pbuf + 32;
    const int tid = threadIdx.x;

    const float* src = (blockIdx.x == 0) ? g_mean : G;
    for (int idx = tid; idx < NN; idx += 256) A[(idx >> 6) * LD + (idx & 63)] = src[idx];
    __syncthreads();
    jacobi64(A, VT, cbuf, sbuf, pbuf, qbuf, SWEEPS_SMALL);
    if (tid < 64) wbuf[tid] = fmaxf(A[tid * LD + tid], EPS);
    __syncthreads();

    if (blockIdx.x == 0) {
        if (tid < 64) fw[tid] = sqrtf(wbuf[tid]);
        __syncthreads();
        recon(VT, fw, B1, B2);
        __syncthreads();
        for (int idx = tid; idx < NN; idx += 256) g_s[idx] = B2[(idx >> 6) * LD + (idx & 63)];
        __syncthreads();
        if (tid < 64) fw[tid] = rsqrtf(wbuf[tid]);
        __syncthreads();
        recon(VT, fw, B1, B2);
        __syncthreads();
        for (int idx = tid; idx < NN; idx += 256) g_si[idx] = B2[(idx >> 6) * LD + (idx & 63)];
    } else {
        if (tid < 64) fw[tid] = sqrtf(wbuf[tid]);
        __syncthreads();
        recon(VT, fw, B1, B2);
        __syncthreads();
        for (int idx = tid; idx < NN; idx += 256) g_gsqrt[idx] = B2[(idx >> 6) * LD + (idx & 63)];
    }
}

// ---------------- kernel 2: per-batch logm(si x si), partial sums ----------------
__global__ __launch_bounds__(256) void batch_log_kernel(const float* __restrict__ x) {
    extern __shared__ float sm[];
    float* sis  = sm;                  // 64*LD
    float* xs   = sis + 64 * LD;       // 64*LD (reused as U)
    float* P    = xs + 64 * LD;        // 64*LD
    float* A    = P + 64 * LD;         // 64*LD
    float* VT   = A + 64 * LD;         // 64*LDV
    float* accum = VT + 64 * LDV;      // 4096
    float* wbuf  = accum + NN;         // 64
    float* cbuf  = wbuf + 64;          // 32
    float* sbuf  = cbuf + 32;          // 32
    unsigned char* pbuf = (unsigned char*)(sbuf + 32);
    unsigned char* qbuf = pbuf + 32;
    const int tid = threadIdx.x;

    for (int idx = tid; idx < NN; idx += 256) sis[(idx >> 6) * LD + (idx & 63)] = g_si[idx];
    for (int idx = tid; idx < NN; idx += 256) accum[idx] = 0.f;
    __syncthreads();

    for (int m = 0; m < K2_NB; ++m) {
        const size_t b = (size_t)blockIdx.x * K2_NB + m;
        const float* xb = x + b * NN;
        for (int idx = tid; idx < NN; idx += 256) xs[(idx >> 6) * LD + (idx & 63)] = xb[idx];
        __syncthreads();
        mm64(sis, xs, P);  __syncthreads();    // P = si @ x
        mm64(P, sis, A);   __syncthreads();    // A = si @ x @ si
        jacobi64(A, VT, cbuf, sbuf, pbuf, qbuf, SWEEPS_BATCH);
        if (tid < 64) wbuf[tid] = logf(fmaxf(A[tid * LD + tid], EPS));
        __syncthreads();
        // U = diag(log w) @ VT  (into xs)
        for (int idx = tid; idx < NN; idx += 256) {
            int k = idx >> 6, i = idx & 63;
            xs[k * LD + i] = wbuf[k] * VT[k * LDV + i];
        }
        __syncthreads();
        // accum += U^T @ VT  ( = V log(w) V^T )
        {
            const int r  = tid >> 2;
            const int c0 = (tid & 3) << 4;
            float acc[16];
#pragma unroll
            for (int i = 0; i < 16; ++i) acc[i] = 0.f;
            for (int k = 0; k < 64; ++k) {
                float u = xs[k * LD + r];
#pragma unroll
                for (int i = 0; i < 16; ++i) acc[i] = fmaf(u, VT[k * LDV + c0 + i], acc[i]);
            }
#pragma unroll
            for (int i = 0; i < 16; ++i) accum[r * 64 + c0 + i] += acc[i];
        }
        __syncthreads();
    }
    for (int idx = tid; idx < NN; idx += 256)
        g_partial_t[(size_t)blockIdx.x * NN + idx] = accum[idx];
}

__global__ void reduce_t_kernel() {
    int j = blockIdx.x * 128 + threadIdx.x;
    float acc = 0.f;
    for (int g = 0; g < K2_BLOCKS; ++g) acc += g_partial_t[(size_t)g * NN + j];
    g_tmean[j] = acc * (1.0f / BATCH);
}

// ---------------- kernel 3: exp(tmean), center, csi, W ----------------
__global__ __launch_bounds__(256) void center_kernel() {
    extern __shared__ float sm[];
    float* A   = sm;
    float* B1  = A + 64 * LD;
    float* B2  = B1 + 64 * LD;
    float* VT  = B2 + 64 * LD;
    float* wbuf = VT + 64 * LDV;
    float* fw   = wbuf + 64;
    float* cbuf = fw + 64;
    float* sbuf = cbuf + 32;
    unsigned char* pbuf = (unsigned char*)(sbuf + 32);
    unsigned char* qbuf = pbuf + 32;
    const int tid = threadIdx.x;

    for (int idx = tid; idx < NN; idx += 256) A[(idx >> 6) * LD + (idx & 63)] = g_tmean[idx];
    __syncthreads();
    jacobi64(A, VT, cbuf, sbuf, pbuf, qbuf, SWEEPS_SMALL);
    if (tid < 64) fw[tid] = expf(A[tid * LD + tid]);   // expm: no clip
    __syncthreads();
    recon(VT, fw, B1, B2);                              // B2 = exp(tmean)
    __syncthreads();
    for (int idx = tid; idx < NN; idx += 256) B1[(idx >> 6) * LD + (idx & 63)] = g_s[idx];
    __syncthreads();
    mm64(B1, B2, A);  __syncthreads();                  // A = s @ E
    mm64(A, B1, B2);  __syncthreads();                  // B2 = s @ E @ s = center
    jacobi64(B2, VT, cbuf, sbuf, pbuf, qbuf, SWEEPS_SMALL);
    if (tid < 64) fw[tid] = rsqrtf(fmaxf(B2[tid * LD + tid], EPS));
    __syncthreads();
    recon(VT, fw, B1, A);                               // A = csi
    __syncthreads();
    for (int idx = tid; idx < NN; idx += 256) B1[(idx >> 6) * LD + (idx & 63)] = g_gsqrt[idx];
    __syncthreads();
    mm64(B1, A, B2);  __syncthreads();                  // B2 = g_sqrt @ csi = W
    for (int idx = tid; idx < NN; idx += 256) g_W[idx] = B2[(idx >> 6) * LD + (idx & 63)];
}

// ---------------- kernel 4: out_b = W x_b W^T ----------------
__global__ __launch_bounds__(256) void output_kernel(const float* __restrict__ x,
                                                     float* __restrict__ out) {
    extern __shared__ float sm[];
    float* Ws = sm;
    float* xs = Ws + 64 * LD;
    float* P  = xs + 64 * LD;
    const int tid = threadIdx.x;
    const size_t b = blockIdx.x;

    for (int idx = tid; idx < NN; idx += 256) Ws[(idx >> 6) * LD + (idx & 63)] = g_W[idx];
    const float* xb = x + b * NN;
    for (int idx = tid; idx < NN; idx += 256) xs[(idx >> 6) * LD + (idx & 63)] = xb[idx];
    __syncthreads();
    mm64(Ws, xs, P);
    __syncthreads();
    const int r  = tid >> 2;
    const int c0 = (tid & 3) << 4;
    float acc[16];
#pragma unroll
    for (int i = 0; i < 16; ++i) acc[i] = 0.f;
    for (int k = 0; k < 64; ++k) {
        float p = P[r * LD + k];
#pragma unroll
        for (int i = 0; i < 16; ++i) acc[i] = fmaf(p, Ws[(c0 + i) * LD + k], acc[i]);
    }
    float* ob = out + b * NN + r * 64 + c0;
#pragma unroll
    for (int i = 0; i < 16; ++i) ob[i] = acc[i];
}

// ---------------- launcher ----------------
extern "C" void kernel_launch(void* const* d_in, const int* in_sizes, int n_in,
                              void* d_out, int out_size) {
    const float* x;
    const float* G;
    if (in_sizes[0] == NN) { G = (const float*)d_in[0]; x = (const float*)d_in[1]; }
    else                   { x = (const float*)d_in[0]; G = (const float*)d_in[1]; }
    float* out = (float*)d_out;

    constexpr size_t SMEM_SMALL = (size_t)(3 * 64 * LD + 64 * LDV + 64 + 64 + 32 + 32) * 4 + 64;
    constexpr size_t SMEM_K2    = (size_t)(4 * 64 * LD + 64 * LDV + NN + 64 + 32 + 32) * 4 + 64;
    constexpr size_t SMEM_K4    = (size_t)(3 * 64 * LD) * 4;

    cudaFuncSetAttribute(prep_kernel,      cudaFuncAttributeMaxDynamicSharedMemorySize, (int)SMEM_SMALL);
    cudaFuncSetAttribute(center_kernel,    cudaFuncAttributeMaxDynamicSharedMemorySize, (int)SMEM_SMALL);
    cudaFuncSetAttribute(batch_log_kernel, cudaFuncAttributeMaxDynamicSharedMemorySize, (int)SMEM_K2);
    cudaFuncSetAttribute(output_kernel,    cudaFuncAttributeMaxDynamicSharedMemorySize, (int)SMEM_K4);

    gen_pairs_kernel<<<1, 1>>>();
    mean_partial_kernel<<<K0_BLOCKS, 256>>>(x);
    reduce_mean_kernel<<<32, 128>>>();
    prep_kernel<<<2, 256, SMEM_SMALL>>>(G);
    batch_log_kernel<<<K2_BLOCKS, 256, SMEM_K2>>>(x);
    reduce_t_kernel<<<32, 128>>>();
    center_kernel<<<1, 256, SMEM_SMALL>>>();
    output_kernel<<<BATCH, 256, SMEM_K4>>>(x, out);
}

// round 2
// speedup vs baseline: 1.8844x; 1.8844x over previous
#include <cuda_runtime.h>
#include <math.h>
#include <stdint.h>

#define BATCH 8192
#define NN 4096
#define LDB 68           // padded stride (floats), float4-aligned
#define EPSF 1e-8f

#define K0_BLOCKS 256
#define K0_NB 32
#define K2_BLOCKS 2048
#define K2_NB 4
#define SWEEPS_BATCH 8
#define SWEEPS_SMALL 10
#define SWEEPS_TS 12

// ---------------- device scratch ----------------
__device__ float g_partial_mean[(size_t)K0_BLOCKS * NN];
__device__ float g_mean[NN];
__device__ float g_s[NN];
__device__ float g_si[NN];
__device__ float g_gsqrt[NN];
__device__ float g_W[NN];
__device__ float g_partial_t[(size_t)K2_BLOCKS * NN];
__device__ float g_tmean[NN];

#define FMA4(acc, sc, b) \
    acc.x = fmaf(sc, b.x, acc.x); acc.y = fmaf(sc, b.y, acc.y); \
    acc.z = fmaf(sc, b.z, acc.z); acc.w = fmaf(sc, b.w, acc.w);

__device__ __forceinline__ float dot8(const float4& a0, const float4& a1,
                                      const float4& b0, const float4& b1) {
    float r = a0.x * b0.x;
    r = fmaf(a0.y, b0.y, r); r = fmaf(a0.z, b0.z, r); r = fmaf(a0.w, b0.w, r);
    r = fmaf(a1.x, b1.x, r); r = fmaf(a1.y, b1.y, r);
    r = fmaf(a1.z, b1.z, r); r = fmaf(a1.w, b1.w, r);
    return r;
}

// global[64x64, stride 64] -> smem[stride LDB]
__device__ __forceinline__ void load_tile(const float* __restrict__ g, float* __restrict__ s) {
    for (int i = threadIdx.x; i < 1024; i += 256) {
        int r = i >> 4, c4 = (i & 15) << 2;
        *(float4*)&s[r * LDB + c4] = *(const float4*)&g[(r << 6) + c4];
    }
}
__device__ __forceinline__ void store_tile(const float* __restrict__ s, float* __restrict__ g) {
    for (int i = threadIdx.x; i < 1024; i += 256) {
        int r = i >> 4, c4 = (i & 15) << 2;
        *(float4*)&g[(r << 6) + c4] = *(const float4*)&s[r * LDB + c4];
    }
}

// C = A @ B, row-major stride LDB inputs; C stride cstride. 256 threads.
__device__ __forceinline__ void mm64f4(const float* __restrict__ A, const float* __restrict__ B,
                                       float* __restrict__ C, int cstride) {
    const int r = threadIdx.x >> 2;
    const int c0 = (threadIdx.x & 3) << 4;
    float4 a0 = {0,0,0,0}, a1 = {0,0,0,0}, a2 = {0,0,0,0}, a3 = {0,0,0,0};
#pragma unroll 4
    for (int k = 0; k < 64; ++k) {
        float a = A[r * LDB + k];
        const float4* br = (const float4*)(B + k * LDB + c0);
        float4 b0 = br[0], b1 = br[1], b2 = br[2], b3 = br[3];
        FMA4(a0, a, b0); FMA4(a1, a, b1); FMA4(a2, a, b2); FMA4(a3, a, b3);
    }
    float4* cp = (float4*)(C + r * cstride + c0);
    cp[0] = a0; cp[1] = a1; cp[2] = a2; cp[3] = a3;
}

// out[r][c] = sum_j Bs[j*LDB+r] * B[j*LDB+c]   (both col-major columns j)
__device__ __forceinline__ void gram_scaled(const float* __restrict__ Bs, const float* __restrict__ B,
                                            float* __restrict__ out, int ostride) {
    const int r = threadIdx.x >> 2;
    const int c0 = (threadIdx.x & 3) << 4;
    float4 a0 = {0,0,0,0}, a1 = {0,0,0,0}, a2 = {0,0,0,0}, a3 = {0,0,0,0};
#pragma unroll 4
    for (int j = 0; j < 64; ++j) {
        float u = Bs[j * LDB + r];
        const float4* br = (const float4*)(B + j * LDB + c0);
        float4 b0 = br[0], b1 = br[1], b2 = br[2], b3 = br[3];
        FMA4(a0, u, b0); FMA4(a1, u, b1); FMA4(a2, u, b2); FMA4(a3, u, b3);
    }
    float4* op = (float4*)(out + r * ostride + c0);
    op[0] = a0; op[1] = a1; op[2] = a2; op[3] = a3;
}

// ---------------- one-sided (Hestenes) Jacobi: col-major B, stride LDB ----------------
// 256 threads; octet (tid>>3) owns pair k; lanes sub=tid&7 own 8 rows each.
// One barrier per round. Caller must sync before entry.
__device__ void jacobi_onesided(float* __restrict__ B, int sweeps) {
    const int tid = threadIdx.x;
    const int k = tid >> 3;
    const int row0 = (tid & 7) << 3;
    for (int sw = 0; sw < sweeps; ++sw) {
        int p = (k == 0) ? 0 : k;
        int q = 63 - k;
        for (int rr = 0; rr < 63; ++rr) {
            float* bp = B + p * LDB + row0;
            float* bq = B + q * LDB + row0;
            float4 p0 = *(float4*)bp, p1 = *(float4*)(bp + 4);
            float4 q0 = *(float4*)bq, q1 = *(float4*)(bq + 4);
            float app = dot8(p0, p1, p0, p1);
            float aqq = dot8(q0, q1, q0, q1);
            float apq = dot8(p0, p1, q0, q1);
#pragma unroll
            for (int d = 4; d > 0; d >>= 1) {
                app += __shfl_xor_sync(0xffffffffu, app, d);
                aqq += __shfl_xor_sync(0xffffffffu, aqq, d);
                apq += __shfl_xor_sync(0xffffffffu, apq, d);
            }
            float c, s;
            if (fabsf(apq) > 1e-30f) {
                float zeta = (aqq - app) / (2.0f * apq);
                float t = copysignf(1.0f, zeta) / (fabsf(zeta) + sqrtf(fmaf(zeta, zeta, 1.0f)));
                c = rsqrtf(fmaf(t, t, 1.0f));
                s = t * c;
            } else { c = 1.0f; s = 0.0f; }
            float4 n0, n1, m0, m1;
            n0.x = c*p0.x - s*q0.x; n0.y = c*p0.y - s*q0.y; n0.z = c*p0.z - s*q0.z; n0.w = c*p0.w - s*q0.w;
            n1.x = c*p1.x - s*q1.x; n1.y = c*p1.y - s*q1.y; n1.z = c*p1.z - s*q1.z; n1.w = c*p1.w - s*q1.w;
            m0.x = s*p0.x + c*q0.x; m0.y = s*p0.y + c*q0.y; m0.z = s*p0.z + c*q0.z; m0.w = s*p0.w + c*q0.w;
            m1.x = s*p1.x + c*q1.x; m1.y = s*p1.y + c*q1.y; m1.z = s*p1.z + c*q1.z; m1.w = s*p1.w + c*q1.w;
            *(float4*)bp = n0; *(float4*)(bp + 4) = n1;
            *(float4*)bq = m0; *(float4*)(bq + 4) = m1;
            if (k) p = (p == 63) ? 1 : p + 1;
            q = (q == 63) ? 1 : q + 1;
            __syncthreads();
        }
    }
}

// column j = tid>>2, segment seg = tid&3 (16 rows); returns ||col||^2, fills v[4].
__device__ __forceinline__ float colnrm2(const float* __restrict__ B, int j, int seg, float4 v[4]) {
    const float4* c = (const float4*)(B + j * LDB + (seg << 4));
    v[0] = c[0]; v[1] = c[1]; v[2] = c[2]; v[3] = c[3];
    float n = v[0].x * v[0].x;
    n = fmaf(v[0].y, v[0].y, n); n = fmaf(v[0].z, v[0].z, n); n = fmaf(v[0].w, v[0].w, n);
    n = fmaf(v[1].x, v[1].x, n); n = fmaf(v[1].y, v[1].y, n); n = fmaf(v[1].z, v[1].z, n); n = fmaf(v[1].w, v[1].w, n);
    n = fmaf(v[2].x, v[2].x, n); n = fmaf(v[2].y, v[2].y, n); n = fmaf(v[2].z, v[2].z, n); n = fmaf(v[2].w, v[2].w, n);
    n = fmaf(v[3].x, v[3].x, n); n = fmaf(v[3].y, v[3].y, n); n = fmaf(v[3].z, v[3].z, n); n = fmaf(v[3].w, v[3].w, n);
    n += __shfl_xor_sync(0xffffffffu, n, 1);
    n += __shfl_xor_sync(0xffffffffu, n, 2);
    return n;
}

__device__ __forceinline__ void scale_store(float* __restrict__ D, int j, int seg,
                                            const float4 v[4], float f) {
    float4* d = (float4*)(D + j * LDB + (seg << 4));
    d[0] = make_float4(f * v[0].x, f * v[0].y, f * v[0].z, f * v[0].w);
    d[1] = make_float4(f * v[1].x, f * v[1].y, f * v[1].z, f * v[1].w);
    d[2] = make_float4(f * v[2].x, f * v[2].y, f * v[2].z, f * v[2].w);
    d[3] = make_float4(f * v[3].x, f * v[3].y, f * v[3].z, f * v[3].w);
}

// ---------------- two-sided Jacobi (only for indefinite tmean) ----------------
__device__ void jacobi_twosided(float* __restrict__ A, float* __restrict__ VT,
                                float* cbuf, float* sbuf, int sweeps) {
    const int tid = threadIdx.x;
    for (int idx = tid; idx < NN; idx += 256) {
        int r = idx >> 6, c = idx & 63;
        VT[r * LDB + c] = (r == c) ? 1.f : 0.f;
    }
    __syncthreads();
    for (int sw = 0; sw < sweeps; ++sw) {
        for (int rr = 0; rr < 63; ++rr) {
            if (tid < 32) {
                int p = (tid == 0) ? 0 : 1 + (tid - 1 + rr) % 63;
                int q = 1 + (62 - tid + rr) % 63;
                float app = A[p * LDB + p], aqq = A[q * LDB + q], apq = A[p * LDB + q];
                float c, s;
                if (fabsf(apq) > 1e-30f) {
                    float th = 0.5f * (aqq - app) / apq;
                    float t = copysignf(1.f, th) / (fabsf(th) + sqrtf(fmaf(th, th, 1.f)));
                    c = rsqrtf(fmaf(t, t, 1.f)); s = t * c;
                } else { c = 1.f; s = 0.f; }
                cbuf[tid] = c; sbuf[tid] = s;
            }
            __syncthreads();
            for (int u = tid; u < 1536; u += 256) {
                if (u < 1024) {
                    int ki = u & 31, kj = u >> 5;
                    int pi = (ki == 0) ? 0 : 1 + (ki - 1 + rr) % 63, qi = 1 + (62 - ki + rr) % 63;
                    int pj = (kj == 0) ? 0 : 1 + (kj - 1 + rr) % 63, qj = 1 + (62 - kj + rr) % 63;
                    float ci = cbuf[ki], si = sbuf[ki], cj = cbuf[kj], sj = sbuf[kj];
                    float a00 = A[pi * LDB + pj], a01 = A[pi * LDB + qj];
                    float a10 = A[qi * LDB + pj], a11 = A[qi * LDB + qj];
                    float b00 = ci * a00 - si * a10, b01 = ci * a01 - si * a11;
                    float b10 = si * a00 + ci * a10, b11 = si * a01 + ci * a11;
                    A[pi * LDB + pj] = cj * b00 - sj * b01;
                    A[pi * LDB + qj] = sj * b00 + cj * b01;
                    A[qi * LDB + pj] = cj * b10 - sj * b11;
                    A[qi * LDB + qj] = sj * b10 + cj * b11;
                } else {
                    int w = u - 1024;
                    int kk = w >> 4, c4 = (w & 15) << 2;
                    int p = (kk == 0) ? 0 : 1 + (kk - 1 + rr) % 63, q = 1 + (62 - kk + rr) % 63;
                    float c = cbuf[kk], s = sbuf[kk];
                    float4 vp = *(float4*)&VT[p * LDB + c4];
                    float4 vq = *(float4*)&VT[q * LDB + c4];
                    float4 np, nq;
                    np.x = c*vp.x - s*vq.x; np.y = c*vp.y - s*vq.y; np.z = c*vp.z - s*vq.z; np.w = c*vp.w - s*vq.w;
                    nq.x = s*vp.x + c*vq.x; nq.y = s*vp.y + c*vq.y; nq.z = s*vp.z + c*vq.z; nq.w = s*vp.w + c*vq.w;
                    *(float4*)&VT[p * LDB + c4] = np;
                    *(float4*)&VT[q * LDB + c4] = nq;
                }
            }
            __syncthreads();
        }
    }
}

// ---------------- kernel 0: arithmetic mean ----------------
__global__ __launch_bounds__(256) void mean_partial_kernel(const float* __restrict__ x) {
    const int g = blockIdx.x, tid = threadIdx.x;
    float4 acc[4] = {{0,0,0,0},{0,0,0,0},{0,0,0,0},{0,0,0,0}};
    const float4* xb = (const float4*)(x + (size_t)g * K0_NB * NN);
    for (int b = 0; b < K0_NB; ++b) {
#pragma unroll
        for (int i = 0; i < 4; ++i) {
            float4 v = xb[(size_t)b * 1024 + tid + (i << 8)];
            acc[i].x += v.x; acc[i].y += v.y; acc[i].z += v.z; acc[i].w += v.w;
        }
    }
    float4* pm = (float4*)(g_partial_mean + (size_t)g * NN);
#pragma unroll
    for (int i = 0; i < 4; ++i) pm[tid + (i << 8)] = acc[i];
}

__global__ void reduce_mean_kernel() {
    int j = blockIdx.x * 128 + threadIdx.x;
    float acc = 0.f;
    for (int g = 0; g < K0_BLOCKS; ++g) acc += g_partial_mean[(size_t)g * NN + j];
    g_mean[j] = acc * (1.0f / BATCH);
}

// ---------------- kernel 1: eigh(mean)->s,si ; eigh(G)->gsqrt (one-sided, SPD) ----------------
__global__ __launch_bounds__(256) void prep_kernel(const float* __restrict__ G) {
    extern __shared__ float sm[];
    float* A   = sm;          // 4352
    float* Bsc = A + 4352;    // 4352
    const int tid = threadIdx.x;
    load_tile(blockIdx.x == 0 ? g_mean : G, A);
    __syncthreads();
    jacobi_onesided(A, SWEEPS_SMALL);
    const int j = tid >> 2, seg = tid & 3;
    float4 v[4];
    float n = colnrm2(A, j, seg, v);
    float lam = fmaxf(sqrtf(n), EPSF);
    float inv_n = 1.0f / n;
    scale_store(Bsc, j, seg, v, sqrtf(lam) * inv_n);
    __syncthreads();
    gram_scaled(Bsc, A, blockIdx.x == 0 ? g_s : g_gsqrt, 64);
    if (blockIdx.x == 0) {
        __syncthreads();
        scale_store(Bsc, j, seg, v, rsqrtf(lam) * inv_n);
        __syncthreads();
        gram_scaled(Bsc, A, g_si, 64);
    }
}

// ---------------- kernel 2: per-batch logm(si x si), partial sums ----------------
__global__ __launch_bounds__(256, 3) void batch_log_kernel(const float* __restrict__ x) {
    extern __shared__ float sm[];
    float* sis   = sm;           // 4352
    float* b1    = sis + 4352;   // 4352
    float* b2    = b1 + 4352;    // 4352
    float* accum = b2 + 4352;    // 4096
    const int tid = threadIdx.x;
    load_tile(g_si, sis);
    for (int i = tid; i < NN; i += 256) accum[i] = 0.f;
    __syncthreads();
    const int r = tid >> 2, c0 = (tid & 3) << 4;
    const int j = tid >> 2, seg = tid & 3;

    for (int m = 0; m < K2_NB; ++m) {
        const float* xb = x + ((size_t)blockIdx.x * K2_NB + m) * NN;
        load_tile(xb, b1);
        __syncthreads();
        mm64f4(sis, b1, b2, LDB);  __syncthreads();   // P = si @ x
        mm64f4(b2, sis, b1, LDB);  __syncthreads();   // A = P @ si (symmetric -> col-major)
        jacobi_onesided(b1, SWEEPS_BATCH);            // ends synced
        {
            float4 v[4];
            float n = colnrm2(b1, j, seg, v);
            float lam = sqrtf(n);
            float f = logf(fmaxf(lam, EPSF)) / n;
            scale_store(b2, j, seg, v, f);
        }
        __syncthreads();
        {   // accum += gram(b2, b1)
            float4 a0 = {0,0,0,0}, a1 = {0,0,0,0}, a2 = {0,0,0,0}, a3 = {0,0,0,0};
#pragma unroll 4
            for (int jj = 0; jj < 64; ++jj) {
                float u = b2[jj * LDB + r];
                const float4* br = (const float4*)(b1 + jj * LDB + c0);
                float4 q0 = br[0], q1 = br[1], q2 = br[2], q3 = br[3];
                FMA4(a0, u, q0); FMA4(a1, u, q1); FMA4(a2, u, q2); FMA4(a3, u, q3);
            }
            float* ac = accum + (r << 6) + c0;
            ac[0] += a0.x;  ac[1] += a0.y;  ac[2]  += a0.z;  ac[3]  += a0.w;
            ac[4] += a1.x;  ac[5] += a1.y;  ac[6]  += a1.z;  ac[7]  += a1.w;
            ac[8] += a2.x;  ac[9] += a2.y;  ac[10] += a2.z;  ac[11] += a2.w;
            ac[12] += a3.x; ac[13] += a3.y; ac[14] += a3.z;  ac[15] += a3.w;
        }
        __syncthreads();
    }
    for (int i = tid; i < NN; i += 256)
        g_partial_t[(size_t)blockIdx.x * NN + i] = accum[i];
}

__global__ void reduce_t_kernel() {
    int j = blockIdx.x * 128 + threadIdx.x;
    float acc = 0.f;
    for (int g = 0; g < K2_BLOCKS; ++g) acc += g_partial_t[(size_t)g * NN + j];
    g_tmean[j] = acc * (1.0f / BATCH);
}

// ---------------- kernel 3: expm(tmean) [two-sided], center, csi, W ----------------
__global__ __launch_bounds__(256) void center_kernel() {
    extern __shared__ float sm[];
    float* A  = sm;          // 4352
    float* VT = A + 4352;    // 4352
    float* T1 = VT + 4352;   // 4352
    float* T2 = T1 + 4352;   // 4352
    float* fw = T2 + 4352;   // 64
    float* cb = fw + 64;     // 32
    float* sb = cb + 32;     // 32
    const int tid = threadIdx.x;

    load_tile(g_tmean, A);
    __syncthreads();
    jacobi_twosided(A, VT, cb, sb, SWEEPS_TS);
    if (tid < 64) fw[tid] = expf(A[tid * LDB + tid]);   // expm: no clip, signed eigs
    __syncthreads();
    for (int idx = tid; idx < NN; idx += 256) {
        int k2 = idx >> 6, i = idx & 63;
        T1[k2 * LDB + i] = fw[k2] * VT[k2 * LDB + i];
    }
    __syncthreads();
    gram_scaled(T1, VT, T2, LDB);       // T2 = expm(tmean)
    __syncthreads();
    load_tile(g_s, A);
    __syncthreads();
    mm64f4(A, T2, T1, LDB);  __syncthreads();  // T1 = s E
    mm64f4(T1, A, T2, LDB);  __syncthreads();  // T2 = center (SPD)
    jacobi_onesided(T2, SWEEPS_SMALL);
    {
        const int j = tid >> 2, seg = tid & 3;
        float4 v[4];
        float n = colnrm2(T2, j, seg, v);
        float lam = fmaxf(sqrtf(n), EPSF);
        float f = rsqrtf(lam) / n;
        scale_store(T1, j, seg, v, f);
    }
    __syncthreads();
    gram_scaled(T1, T2, A, LDB);        // A = csi
    __syncthreads();
    load_tile(g_gsqrt, VT);
    __syncthreads();
    mm64f4(VT, A, T1, LDB);             // T1 = g_sqrt @ csi = W
    __syncthreads();
    store_tile(T1, g_W);
}

// ---------------- kernel 4: out_b = W x_b W^T ----------------
__global__ __launch_bounds__(256) void output_kernel(const float* __restrict__ x,
                                                     float* __restrict__ out) {
    extern __shared__ float sm[];
    float* Ws = sm;          // 4352
    float* WT = Ws + 4352;   // 4352
    float* xs = WT + 4352;   // 4352
    float* P  = xs + 4352;   // 4352
    const int tid = threadIdx.x;
    load_tile(g_W, Ws);
    for (int i = tid; i < NN; i += 256) WT[(i & 63) * LDB + (i >> 6)] = g_W[i];
    load_tile(x + (size_t)blockIdx.x * NN, xs);
    __syncthreads();
    mm64f4(Ws, xs, P, LDB);             // P = W @ x
    __syncthreads();
    mm64f4(P, WT, out + (size_t)blockIdx.x * NN, 64);   // out = P @ W^T
}

// ---------------- launcher ----------------
extern "C" void kernel_launch(void* const* d_in, const int* in_sizes, int n_in,
                              void* d_out, int out_size) {
    const float* x;
    const float* G;
    if (in_sizes[0] == NN) { G = (const float*)d_in[0]; x = (const float*)d_in[1]; }
    else                   { x = (const float*)d_in[0]; G = (const float*)d_in[1]; }
    float* out = (float*)d_out;

    constexpr size_t SM_PREP   = (size_t)(2 * 4352) * 4;
    constexpr size_t SM_BATCH  = (size_t)(3 * 4352 + NN) * 4;
    constexpr size_t SM_CENTER = (size_t)(4 * 4352 + 64 + 32 + 32) * 4;
    constexpr size_t SM_OUT    = (size_t)(4 * 4352) * 4;

    cudaFuncSetAttribute(batch_log_kernel, cudaFuncAttributeMaxDynamicSharedMemorySize, (int)SM_BATCH);
    cudaFuncSetAttribute(center_kernel,    cudaFuncAttributeMaxDynamicSharedMemorySize, (int)SM_CENTER);
    cudaFuncSetAttribute(output_kernel,    cudaFuncAttributeMaxDynamicSharedMemorySize, (int)SM_OUT);

    mean_partial_kernel<<<K0_BLOCKS, 256>>>(x);
    reduce_mean_kernel<<<32, 128>>>();
    prep_kernel<<<2, 256, SM_PREP>>>(G);
    batch_log_kernel<<<K2_BLOCKS, 256, SM_BATCH>>>(x);
    reduce_t_kernel<<<32, 128>>>();
    center_kernel<<<1, 256, SM_CENTER>>>();
    output_kernel<<<BATCH, 256, SM_OUT>>>(x, out);
}

// round 3
// speedup vs baseline: 2.7591x; 1.4642x over previous
#include <cuda_runtime.h>
#include <math.h>
#include <stdint.h>

#define BATCH 8192
#define NN 4096
#define LDB 68           // padded stride (floats), float4-aligned
#define EPSF 1e-8f

#define K0_BLOCKS 256
#define K0_NB 32
#define K2_BLOCKS 2048
#define K2_NB 4
#define SWEEPS_BATCH 7
#define SWEEPS_SMALL 10
#define SWEEPS_TS 12

// ---------------- device scratch ----------------
__device__ float g_partial_mean[(size_t)K0_BLOCKS * NN];
__device__ float g_mean[NN];
__device__ float g_s[NN];
__device__ float g_si[NN];
__device__ float g_gsqrt[NN];
__device__ float g_W[NN];
__device__ float g_partial_t[(size_t)K2_BLOCKS * NN];
__device__ float g_tmean[NN];

#define FMA4(acc, sc, b) \
    acc.x = fmaf(sc, b.x, acc.x); acc.y = fmaf(sc, b.y, acc.y); \
    acc.z = fmaf(sc, b.z, acc.z); acc.w = fmaf(sc, b.w, acc.w);

__device__ __forceinline__ float dot8(const float4& a0, const float4& a1,
                                      const float4& b0, const float4& b1) {
    float r = a0.x * b0.x;
    r = fmaf(a0.y, b0.y, r); r = fmaf(a0.z, b0.z, r); r = fmaf(a0.w, b0.w, r);
    r = fmaf(a1.x, b1.x, r); r = fmaf(a1.y, b1.y, r);
    r = fmaf(a1.z, b1.z, r); r = fmaf(a1.w, b1.w, r);
    return r;
}

// global[64x64, stride 64] -> smem[stride LDB]
__device__ __forceinline__ void load_tile(const float* __restrict__ g, float* __restrict__ s) {
    for (int i = threadIdx.x; i < 1024; i += 256) {
        int r = i >> 4, c4 = (i & 15) << 2;
        *(float4*)&s[r * LDB + c4] = *(const float4*)&g[(r << 6) + c4];
    }
}
__device__ __forceinline__ void store_tile(const float* __restrict__ s, float* __restrict__ g) {
    for (int i = threadIdx.x; i < 1024; i += 256) {
        int r = i >> 4, c4 = (i & 15) << 2;
        *(float4*)&g[(r << 6) + c4] = *(const float4*)&s[r * LDB + c4];
    }
}

// C = A @ B, row-major stride LDB inputs; C stride cstride. 256 threads.
__device__ __forceinline__ void mm64f4(const float* __restrict__ A, const float* __restrict__ B,
                                       float* __restrict__ C, int cstride) {
    const int r = threadIdx.x >> 2;
    const int c0 = (threadIdx.x & 3) << 4;
    float4 a0 = {0,0,0,0}, a1 = {0,0,0,0}, a2 = {0,0,0,0}, a3 = {0,0,0,0};
#pragma unroll 4
    for (int k = 0; k < 64; ++k) {
        float a = A[r * LDB + k];
        const float4* br = (const float4*)(B + k * LDB + c0);
        float4 b0 = br[0], b1 = br[1], b2 = br[2], b3 = br[3];
        FMA4(a0, a, b0); FMA4(a1, a, b1); FMA4(a2, a, b2); FMA4(a3, a, b3);
    }
    float4* cp = (float4*)(C + r * cstride + c0);
    cp[0] = a0; cp[1] = a1; cp[2] = a2; cp[3] = a3;
}

// out[r][c] = sum_j Bs[j*LDB+r] * B[j*LDB+c]
__device__ __forceinline__ void gram_scaled(const float* __restrict__ Bs, const float* __restrict__ B,
                                            float* __restrict__ out, int ostride) {
    const int r = threadIdx.x >> 2;
    const int c0 = (threadIdx.x & 3) << 4;
    float4 a0 = {0,0,0,0}, a1 = {0,0,0,0}, a2 = {0,0,0,0}, a3 = {0,0,0,0};
#pragma unroll 4
    for (int j = 0; j < 64; ++j) {
        float u = Bs[j * LDB + r];
        const float4* br = (const float4*)(B + j * LDB + c0);
        float4 b0 = br[0], b1 = br[1], b2 = br[2], b3 = br[3];
        FMA4(a0, u, b0); FMA4(a1, u, b1); FMA4(a2, u, b2); FMA4(a3, u, b3);
    }
    float4* op = (float4*)(out + r * ostride + c0);
    op[0] = a0; op[1] = a1; op[2] = a2; op[3] = a3;
}

// ---------------- one-sided (Hestenes) Jacobi: col-major B, stride LDB ----------------
// 256 threads; octet (tid>>3) owns pair k; lane sub=tid&7 handles rows
// [4*sub, 4*sub+3] and [32+4*sub, 35+4*sub]  -> 8-lane phases cover 32
// consecutive words = all 32 banks: conflict-free LDS/STS.128.
__device__ void jacobi_onesided(float* __restrict__ B, int sweeps) {
    const int tid = threadIdx.x;
    const int k = tid >> 3;
    const int o0 = (tid & 7) << 2;
    const int o1 = 32 + o0;
    for (int sw = 0; sw < sweeps; ++sw) {
        int p = (k == 0) ? 0 : k;
        int q = 63 - k;
        for (int rr = 0; rr < 63; ++rr) {
            float* bp = B + p * LDB;
            float* bq = B + q * LDB;
            float4 p0 = *(float4*)(bp + o0), p1 = *(float4*)(bp + o1);
            float4 q0 = *(float4*)(bq + o0), q1 = *(float4*)(bq + o1);
            float app = dot8(p0, p1, p0, p1);
            float aqq = dot8(q0, q1, q0, q1);
            float apq = dot8(p0, p1, q0, q1);
#pragma unroll
            for (int d = 4; d > 0; d >>= 1) {
                app += __shfl_xor_sync(0xffffffffu, app, d);
                aqq += __shfl_xor_sync(0xffffffffu, aqq, d);
                apq += __shfl_xor_sync(0xffffffffu, apq, d);
            }
            float c, s;
            if (fabsf(apq) > 1e-30f) {
                float zeta = (aqq - app) / (2.0f * apq);
                float t = copysignf(1.0f, zeta) / (fabsf(zeta) + sqrtf(fmaf(zeta, zeta, 1.0f)));
                c = rsqrtf(fmaf(t, t, 1.0f));
                s = t * c;
            } else { c = 1.0f; s = 0.0f; }
            float4 n0, n1, m0, m1;
            n0.x = c*p0.x - s*q0.x; n0.y = c*p0.y - s*q0.y; n0.z = c*p0.z - s*q0.z; n0.w = c*p0.w - s*q0.w;
            n1.x = c*p1.x - s*q1.x; n1.y = c*p1.y - s*q1.y; n1.z = c*p1.z - s*q1.z; n1.w = c*p1.w - s*q1.w;
            m0.x = s*p0.x + c*q0.x; m0.y = s*p0.y + c*q0.y; m0.z = s*p0.z + c*q0.z; m0.w = s*p0.w + c*q0.w;
            m1.x = s*p1.x + c*q1.x; m1.y = s*p1.y + c*q1.y; m1.z = s*p1.z + c*q1.z; m1.w = s*p1.w + c*q1.w;
            *(float4*)(bp + o0) = n0; *(float4*)(bp + o1) = n1;
            *(float4*)(bq + o0) = m0; *(float4*)(bq + o1) = m1;
            if (k) p = (p == 63) ? 1 : p + 1;
            q = (q == 63) ? 1 : q + 1;
            __syncthreads();
        }
    }
}

// column j = tid>>2, segment seg = tid&3 (16 rows); returns ||col||^2, fills v[4].
__device__ __forceinline__ float colnrm2(const float* __restrict__ B, int j, int seg, float4 v[4]) {
    const float4* c = (const float4*)(B + j * LDB + (seg << 4));
    v[0] = c[0]; v[1] = c[1]; v[2] = c[2]; v[3] = c[3];
    float n = v[0].x * v[0].x;
    n = fmaf(v[0].y, v[0].y, n); n = fmaf(v[0].z, v[0].z, n); n = fmaf(v[0].w, v[0].w, n);
    n = fmaf(v[1].x, v[1].x, n); n = fmaf(v[1].y, v[1].y, n); n = fmaf(v[1].z, v[1].z, n); n = fmaf(v[1].w, v[1].w, n);
    n = fmaf(v[2].x, v[2].x, n); n = fmaf(v[2].y, v[2].y, n); n = fmaf(v[2].z, v[2].z, n); n = fmaf(v[2].w, v[2].w, n);
    n = fmaf(v[3].x, v[3].x, n); n = fmaf(v[3].y, v[3].y, n); n = fmaf(v[3].z, v[3].z, n); n = fmaf(v[3].w, v[3].w, n);
    n += __shfl_xor_sync(0xffffffffu, n, 1);
    n += __shfl_xor_sync(0xffffffffu, n, 2);
    return n;
}

__device__ __forceinline__ void scale_store(float* __restrict__ D, int j, int seg,
                                            const float4 v[4], float f) {
    float4* d = (float4*)(D + j * LDB + (seg << 4));
    d[0] = make_float4(f * v[0].x, f * v[0].y, f * v[0].z, f * v[0].w);
    d[1] = make_float4(f * v[1].x, f * v[1].y, f * v[1].z, f * v[1].w);
    d[2] = make_float4(f * v[2].x, f * v[2].y, f * v[2].z, f * v[2].w);
    d[3] = make_float4(f * v[3].x, f * v[3].y, f * v[3].z, f * v[3].w);
}

// ---------------- two-sided Jacobi (only for indefinite tmean) ----------------
__device__ void jacobi_twosided(float* __restrict__ A, float* __restrict__ VT,
                                float* cbuf, float* sbuf, int sweeps) {
    const int tid = threadIdx.x;
    for (int idx = tid; idx < NN; idx += 256) {
        int r = idx >> 6, c = idx & 63;
        VT[r * LDB + c] = (r == c) ? 1.f : 0.f;
    }
    __syncthreads();
    for (int sw = 0; sw < sweeps; ++sw) {
        for (int rr = 0; rr < 63; ++rr) {
            if (tid < 32) {
                int p = (tid == 0) ? 0 : 1 + (tid - 1 + rr) % 63;
                int q = 1 + (62 - tid + rr) % 63;
                float app = A[p * LDB + p], aqq = A[q * LDB + q], apq = A[p * LDB + q];
                float c, s;
                if (fabsf(apq) > 1e-30f) {
                    float th = 0.5f * (aqq - app) / apq;
                    float t = copysignf(1.f, th) / (fabsf(th) + sqrtf(fmaf(th, th, 1.f)));
                    c = rsqrtf(fmaf(t, t, 1.f)); s = t * c;
                } else { c = 1.f; s = 0.f; }
                cbuf[tid] = c; sbuf[tid] = s;
            }
            __syncthreads();
            for (int u = tid; u < 1536; u += 256) {
                if (u < 1024) {
                    int ki = u & 31, kj = u >> 5;
                    int pi = (ki == 0) ? 0 : 1 + (ki - 1 + rr) % 63, qi = 1 + (62 - ki + rr) % 63;
                    int pj = (kj == 0) ? 0 : 1 + (kj - 1 + rr) % 63, qj = 1 + (62 - kj + rr) % 63;
                    float ci = cbuf[ki], si = sbuf[ki], cj = cbuf[kj], sj = sbuf[kj];
                    float a00 = A[pi * LDB + pj], a01 = A[pi * LDB + qj];
                    float a10 = A[qi * LDB + pj], a11 = A[qi * LDB + qj];
                    float b00 = ci * a00 - si * a10, b01 = ci * a01 - si * a11;
                    float b10 = si * a00 + ci * a10, b11 = si * a01 + ci * a11;
                    A[pi * LDB + pj] = cj * b00 - sj * b01;
                    A[pi * LDB + qj] = sj * b00 + cj * b01;
                    A[qi * LDB + pj] = cj * b10 - sj * b11;
                    A[qi * LDB + qj] = sj * b10 + cj * b11;
                } else {
                    int w = u - 1024;
                    int kk = w >> 4, c4 = (w & 15) << 2;
                    int p = (kk == 0) ? 0 : 1 + (kk - 1 + rr) % 63, q = 1 + (62 - kk + rr) % 63;
                    float c = cbuf[kk], s = sbuf[kk];
                    float4 vp = *(float4*)&VT[p * LDB + c4];
                    float4 vq = *(float4*)&VT[q * LDB + c4];
                    float4 np, nq;
                    np.x = c*vp.x - s*vq.x; np.y = c*vp.y - s*vq.y; np.z = c*vp.z - s*vq.z; np.w = c*vp.w - s*vq.w;
                    nq.x = s*vp.x + c*vq.x; nq.y = s*vp.y + c*vq.y; nq.z = s*vp.z + c*vq.z; nq.w = s*vp.w + c*vq.w;
                    *(float4*)&VT[p * LDB + c4] = np;
                    *(float4*)&VT[q * LDB + c4] = nq;
                }
            }
            __syncthreads();
        }
    }
}

// ---------------- kernel 0: arithmetic mean ----------------
__global__ __launch_bounds__(256) void mean_partial_kernel(const float* __restrict__ x) {
    const int g = blockIdx.x, tid = threadIdx.x;
    float4 acc[4] = {{0,0,0,0},{0,0,0,0},{0,0,0,0},{0,0,0,0}};
    const float4* xb = (const float4*)(x + (size_t)g * K0_NB * NN);
    for (int b = 0; b < K0_NB; ++b) {
#pragma unroll
        for (int i = 0; i < 4; ++i) {
            float4 v = xb[(size_t)b * 1024 + tid + (i << 8)];
            acc[i].x += v.x; acc[i].y += v.y; acc[i].z += v.z; acc[i].w += v.w;
        }
    }
    float4* pm = (float4*)(g_partial_mean + (size_t)g * NN);
#pragma unroll
    for (int i = 0; i < 4; ++i) pm[tid + (i << 8)] = acc[i];
}

__global__ void reduce_mean_kernel() {
    int j = blockIdx.x * 128 + threadIdx.x;
    float acc = 0.f;
    for (int g = 0; g < K0_BLOCKS; ++g) acc += g_partial_mean[(size_t)g * NN + j];
    g_mean[j] = acc * (1.0f / BATCH);
}

// ---------------- kernel 1: eigh(mean)->s,si ; eigh(G)->gsqrt ----------------
__global__ __launch_bounds__(256) void prep_kernel(const float* __restrict__ G) {
    extern __shared__ float sm[];
    float* A   = sm;
    float* Bsc = A + 4352;
    const int tid = threadIdx.x;
    load_tile(blockIdx.x == 0 ? g_mean : G, A);
    __syncthreads();
    jacobi_onesided(A, SWEEPS_SMALL);
    const int j = tid >> 2, seg = tid & 3;
    float4 v[4];
    float n = colnrm2(A, j, seg, v);
    float lam = fmaxf(sqrtf(n), EPSF);
    float inv_n = 1.0f / n;
    scale_store(Bsc, j, seg, v, sqrtf(lam) * inv_n);
    __syncthreads();
    gram_scaled(Bsc, A, blockIdx.x == 0 ? g_s : g_gsqrt, 64);
    if (blockIdx.x == 0) {
        __syncthreads();
        scale_store(Bsc, j, seg, v, rsqrtf(lam) * inv_n);
        __syncthreads();
        gram_scaled(Bsc, A, g_si, 64);
    }
}

// ---------------- kernel 2: per-batch logm(si x si), partial sums ----------------
__global__ __launch_bounds__(256, 3) void batch_log_kernel(const float* __restrict__ x) {
    extern __shared__ float sm[];
    float* sis = sm;           // 4352
    float* b1  = sis + 4352;   // 4352
    float* b2  = b1 + 4352;    // 4352
    float* fbuf = b2 + 4352;   // 64 per-column log scale factors
    const int tid = threadIdx.x;
    load_tile(g_si, sis);
    __syncthreads();
    const int r = tid >> 2, c0 = (tid & 3) << 4;
    const int j = tid >> 2, seg = tid & 3;
    float4 t0 = {0,0,0,0}, t1 = {0,0,0,0}, t2 = {0,0,0,0}, t3 = {0,0,0,0};  // persistent accum

    for (int m = 0; m < K2_NB; ++m) {
        const float* xb = x + ((size_t)blockIdx.x * K2_NB + m) * NN;
        load_tile(xb, b1);
        __syncthreads();
        mm64f4(sis, b1, b2, LDB);  __syncthreads();   // P = si @ x
        mm64f4(b2, sis, b1, LDB);  __syncthreads();   // A = P @ si (symmetric)
        jacobi_onesided(b1, SWEEPS_BATCH);            // cols b_j = lam_j u_j
        {
            float4 v[4];
            float n = colnrm2(b1, j, seg, v);
            if (seg == 0) {
                float lam = sqrtf(n);
                fbuf[j] = logf(fmaxf(lam, EPSF)) / n;   // log(lam)/lam^2
            }
        }
        __syncthreads();
        {   // t += sum_j f_j * b_j b_j^T  (row tile r, cols c0..c0+15)
#pragma unroll 4
            for (int jj = 0; jj < 64; ++jj) {
                float u = fbuf[jj] * b1[jj * LDB + r];
                const float4* br = (const float4*)(b1 + jj * LDB + c0);
                float4 q0 = br[0], q1 = br[1], q2 = br[2], q3 = br[3];
                FMA4(t0, u, q0); FMA4(t1, u, q1); FMA4(t2, u, q2); FMA4(t3, u, q3);
            }
        }
        __syncthreads();
    }
    float4* pt = (float4*)(g_partial_t + (size_t)blockIdx.x * NN + (r << 6) + c0);
    pt[0] = t0; pt[1] = t1; pt[2] = t2; pt[3] = t3;
}

__global__ void reduce_t_kernel() {
    int j = blockIdx.x * 128 + threadIdx.x;
    float acc = 0.f;
    for (int g = 0; g < K2_BLOCKS; ++g) acc += g_partial_t[(size_t)g * NN + j];
    g_tmean[j] = acc * (1.0f / BATCH);
}

// ---------------- kernel 3: expm(tmean) [two-sided], center, csi, W ----------------
__global__ __launch_bounds__(256) void center_kernel() {
    extern __shared__ float sm[];
    float* A  = sm;
    float* VT = A + 4352;
    float* T1 = VT + 4352;
    float* T2 = T1 + 4352;
    float* fw = T2 + 4352;
    float* cb = fw + 64;
    float* sb = cb + 32;
    const int tid = threadIdx.x;

    load_tile(g_tmean, A);
    __syncthreads();
    jacobi_twosided(A, VT, cb, sb, SWEEPS_TS);
    if (tid < 64) fw[tid] = expf(A[tid * LDB + tid]);
    __syncthreads();
    for (int idx = tid; idx < NN; idx += 256) {
        int k2 = idx >> 6, i = idx & 63;
        T1[k2 * LDB + i] = fw[k2] * VT[k2 * LDB + i];
    }
    __syncthreads();
    gram_scaled(T1, VT, T2, LDB);       // T2 = expm(tmean)
    __syncthreads();
    load_tile(g_s, A);
    __syncthreads();
    mm64f4(A, T2, T1, LDB);  __syncthreads();  // T1 = s E
    mm64f4(T1, A, T2, LDB);  __syncthreads();  // T2 = center (SPD)
    jacobi_onesided(T2, SWEEPS_SMALL);
    {
        const int j = tid >> 2, seg = tid & 3;
        float4 v[4];
        float n = colnrm2(T2, j, seg, v);
        float lam = fmaxf(sqrtf(n), EPSF);
        float f = rsqrtf(lam) / n;
        scale_store(T1, j, seg, v, f);
    }
    __syncthreads();
    gram_scaled(T1, T2, A, LDB);        // A = csi
    __syncthreads();
    load_tile(g_gsqrt, VT);
    __syncthreads();
    mm64f4(VT, A, T1, LDB);             // T1 = g_sqrt @ csi = W
    __syncthreads();
    store_tile(T1, g_W);
}

// ---------------- kernel 4: out_b = W x_b W^T ----------------
__global__ __launch_bounds__(256) void output_kernel(const float* __restrict__ x,
                                                     float* __restrict__ out) {
    extern __shared__ float sm[];
    float* Ws = sm;
    float* WT = Ws + 4352;
    float* xs = WT + 4352;
    float* P  = xs + 4352;
    const int tid = threadIdx.x;
    load_tile(g_W, Ws);
    for (int i = tid; i < NN; i += 256) WT[(i & 63) * LDB + (i >> 6)] = g_W[i];
    load_tile(x + (size_t)blockIdx.x * NN, xs);
    __syncthreads();
    mm64f4(Ws, xs, P, LDB);             // P = W @ x
    __syncthreads();
    mm64f4(P, WT, out + (size_t)blockIdx.x * NN, 64);   // out = P @ W^T
}

// ---------------- launcher ----------------
extern "C" void kernel_launch(void* const* d_in, const int* in_sizes, int n_in,
                              void* d_out, int out_size) {
    const float* x;
    const float* G;
    if (in_sizes[0] == NN) { G = (const float*)d_in[0]; x = (const float*)d_in[1]; }
    else                   { x = (const float*)d_in[0]; G = (const float*)d_in[1]; }
    float* out = (float*)d_out;

    constexpr size_t SM_PREP   = (size_t)(2 * 4352) * 4;
    constexpr size_t SM_BATCH  = (size_t)(3 * 4352 + 64) * 4;
    constexpr size_t SM_CENTER = (size_t)(4 * 4352 + 64 + 32 + 32) * 4;
    constexpr size_t SM_OUT    = (size_t)(4 * 4352) * 4;

    cudaFuncSetAttribute(batch_log_kernel, cudaFuncAttributeMaxDynamicSharedMemorySize, (int)SM_BATCH);
    cudaFuncSetAttribute(center_kernel,    cudaFuncAttributeMaxDynamicSharedMemorySize, (int)SM_CENTER);
    cudaFuncSetAttribute(output_kernel,    cudaFuncAttributeMaxDynamicSharedMemorySize, (int)SM_OUT);

    mean_partial_kernel<<<K0_BLOCKS, 256>>>(x);
    reduce_mean_kernel<<<32, 128>>>();
    prep_kernel<<<2, 256, SM_PREP>>>(G);
    batch_log_kernel<<<K2_BLOCKS, 256, SM_BATCH>>>(x);
    reduce_t_kernel<<<32, 128>>>();
    center_kernel<<<1, 256, SM_CENTER>>>();
    output_kernel<<<BATCH, 256, SM_OUT>>>(x, out);
}